// round 14
// baseline (speedup 1.0000x reference)
#include <cuda_runtime.h>
#include <cuda_bf16.h>
#include <cstdint>

#define B_  1024
#define I_  256
#define N_  512
#define D_  6
#define U_  16
#define L_  64
#define ND_ (N_ * D_)   // 3072

__device__ __nv_bfloat16 g_Wh[ND_ * I_];     // W transposed hi, [m][k]
__device__ __nv_bfloat16 g_Wl[ND_ * I_];     // W transposed lo, [m][k]
__device__ __nv_bfloat16 g_xh[B_ * I_];      // x hi, [j][k]
__device__ __nv_bfloat16 g_xl[B_ * I_];      // x lo, [j][k]
__device__ float g_Ht[ND_ * B_];             // sparsemoid bins h, [m][j]
__device__ float g_sc [ND_];                 // 0.5*exp(-lt)
__device__ float g_of [ND_];                 // 0.5 - th*0.5*exp(-lt)
__device__ uint32_t g_respP[N_ * U_ * L_];   // resp, tf32 bits, pair-interleaved

__device__ __forceinline__ uint32_t tf32r(float x) {
    uint32_t r; asm("cvt.rna.tf32.f32 %0, %1;" : "=r"(r) : "f"(x)); return r;
}

__device__ __forceinline__ void mma_tf32(float c[4], uint32_t a0, uint32_t a1,
                                         uint32_t a2, uint32_t a3,
                                         uint32_t b0, uint32_t b1) {
    asm volatile(
        "mma.sync.aligned.m16n8k8.row.col.f32.tf32.tf32.f32 "
        "{%0,%1,%2,%3}, {%4,%5,%6,%7}, {%8,%9}, {%0,%1,%2,%3};"
        : "+f"(c[0]), "+f"(c[1]), "+f"(c[2]), "+f"(c[3])
        : "r"(a0), "r"(a1), "r"(a2), "r"(a3), "r"(b0), "r"(b1));
}

__device__ __forceinline__ void mma_bf16(float c[4], uint32_t a0, uint32_t a1,
                                         uint32_t a2, uint32_t a3,
                                         uint32_t b0, uint32_t b1) {
    asm volatile(
        "mma.sync.aligned.m16n8k16.row.col.f32.bf16.bf16.f32 "
        "{%0,%1,%2,%3}, {%4,%5,%6,%7}, {%8,%9}, {%0,%1,%2,%3};"
        : "+f"(c[0]), "+f"(c[1]), "+f"(c[2]), "+f"(c[3])
        : "r"(a0), "r"(a1), "r"(a2), "r"(a3), "r"(b0), "r"(b1));
}

// ---------------------------------------------------------------------------
// Kernel P: fused prep (unchanged from R13). 512 x 256.
// ---------------------------------------------------------------------------
__global__ void __launch_bounds__(256) k_prep(const float* __restrict__ fsl,
                                              const float* __restrict__ x,
                                              const float* __restrict__ th,
                                              const float* __restrict__ lt,
                                              const float* __restrict__ resp) {
    __shared__ float fsm[48][33];   // [m_local][i_local]

    int t   = threadIdx.x;
    int bid = blockIdx.x;
    int gt  = bid * 256 + t;

    // ---- sparsemax for (i, n) = (it*32+li, nt*8+ln) ----
    int it = bid >> 6;       // 0..7
    int nt = bid & 63;       // 0..63
    int li = t >> 3, ln = t & 7;
    {
        const float2* z2 = (const float2*)(fsl + ((size_t)(it * 32 + li) * N_ + nt * 8 + ln) * D_);
        float2 za = z2[0], zb = z2[1], zc = z2[2];
        float z0 = za.x, z1 = za.y, z2v = zb.x, z3 = zb.y, z4 = zc.x, z5 = zc.y;
        float s0 = z0, s1 = z1, s2 = z2v, s3 = z3, s4 = z4, s5 = z5;
#define CSWP(a, b) { float _mx = fmaxf(a, b); float _mn = fminf(a, b); a = _mx; b = _mn; }
        CSWP(s1, s2) CSWP(s4, s5) CSWP(s0, s2) CSWP(s3, s5)
        CSWP(s0, s1) CSWP(s3, s4) CSWP(s2, s5) CSWP(s0, s3)
        CSWP(s1, s4) CSWP(s2, s4) CSWP(s1, s3) CSWP(s2, s3)
#undef CSWP
        float cs = s0; int k = 1; float ts = cs;
        cs += s1; if (1.0f + 2.0f * s1 > cs) { k = 2; ts = cs; }
        cs += s2; if (1.0f + 3.0f * s2 > cs) { k = 3; ts = cs; }
        cs += s3; if (1.0f + 4.0f * s3 > cs) { k = 4; ts = cs; }
        cs += s4; if (1.0f + 5.0f * s4 > cs) { k = 5; ts = cs; }
        cs += s5; if (1.0f + 6.0f * s5 > cs) { k = 6; ts = cs; }
        float tau = (ts - 1.0f) / (float)k;

        fsm[ln * 6 + 0][li] = fmaxf(z0 - tau, 0.0f);
        fsm[ln * 6 + 1][li] = fmaxf(z1 - tau, 0.0f);
        fsm[ln * 6 + 2][li] = fmaxf(z2v - tau, 0.0f);
        fsm[ln * 6 + 3][li] = fmaxf(z3 - tau, 0.0f);
        fsm[ln * 6 + 4][li] = fmaxf(z4 - tau, 0.0f);
        fsm[ln * 6 + 5][li] = fmaxf(z5 - tau, 0.0f);
    }

    // ---- resp -> tf32 pair-interleaved, gather form ----
    {
        int fi = gt * 4;
        int nu = fi >> 6;
        int cc = (fi & 63) >> 2;
        int s = cc >> 1, half = cc & 1;
        const float* r = resp + (size_t)nu * 64 + 8 * s + 2 * half;
        float2 ra = *(const float2*)(r);
        float2 rb = *(const float2*)(r + 4);
        uint4 o;
        o.x = tf32r(ra.x);
        o.y = tf32r(rb.x);
        o.z = tf32r(ra.y);
        o.w = tf32r(rb.y);
        *(uint4*)(g_respP + fi) = o;
    }

    if (gt < (B_ * I_) / 4) {   // x split
        float4 v = ((const float4*)x)[gt];
        float f[4] = { v.x, v.y, v.z, v.w };
        __nv_bfloat16 h[4], l[4];
#pragma unroll
        for (int i = 0; i < 4; i++) {
            h[i] = __float2bfloat16_rn(f[i]);
            l[i] = __float2bfloat16_rn(f[i] - __bfloat162float(h[i]));
        }
        __nv_bfloat162 h01(h[0], h[1]), h23(h[2], h[3]);
        __nv_bfloat162 l01(l[0], l[1]), l23(l[2], l[3]);
        uint2 uh = make_uint2(*reinterpret_cast<uint32_t*>(&h01),
                              *reinterpret_cast<uint32_t*>(&h23));
        uint2 ul = make_uint2(*reinterpret_cast<uint32_t*>(&l01),
                              *reinterpret_cast<uint32_t*>(&l23));
        *(uint2*)(g_xh + (size_t)gt * 4) = uh;
        *(uint2*)(g_xl + (size_t)gt * 4) = ul;
    }

    if (gt < ND_) {   // scale/offset
        float s = 0.5f * expf(-lt[gt]);
        g_sc[gt] = s;
        g_of[gt] = 0.5f - th[gt] * s;
    }

    // ---- emit transposed bf16 W ----
    __syncthreads();
    {
        int w = t >> 5, lane = t & 31;
#pragma unroll
        for (int r2 = 0; r2 < 6; r2++) {
            int r = w * 6 + r2;
            float v = fsm[r][lane];
            __nv_bfloat16 hi = __float2bfloat16_rn(v);
            __nv_bfloat16 lo = __float2bfloat16_rn(v - __bfloat162float(hi));
            size_t o = (size_t)(nt * 48 + r) * I_ + it * 32 + lane;
            g_Wh[o] = hi;
            g_Wl[o] = lo;
        }
    }
}

// ---------------------------------------------------------------------------
// Kernel B: tensor GEMM + sparsemoid epilogue -> g_Ht holds h directly.
// ---------------------------------------------------------------------------
__global__ void __launch_bounds__(256) k_gemm() {
    __shared__ __nv_bfloat16 Wh_s[128][72], Wl_s[128][72];
    __shared__ __nv_bfloat16 Xh_s[64][72],  Xl_s[64][72];

    int t    = threadIdx.x;
    int w    = t >> 5;
    int lane = t & 31;
    int g    = lane >> 2;
    int tig  = lane & 3;
    int jt   = blockIdx.x;
    int mt   = blockIdx.y;

    float acc[8][4];
#pragma unroll
    for (int jf = 0; jf < 8; jf++)
#pragma unroll
        for (int i = 0; i < 4; i++) acc[jf][i] = 0.0f;

    for (int kc = 0; kc < I_; kc += 64) {
        __syncthreads();
        {
#pragma unroll
            for (int i = 0; i < 4; i++) {
                int idx = t + i * 256;
                int row = idx >> 3, seg = idx & 7;
                size_t go = (size_t)(mt * 128 + row) * I_ + kc + seg * 8;
                *(uint4*)&Wh_s[row][seg * 8] = *(const uint4*)(g_Wh + go);
                *(uint4*)&Wl_s[row][seg * 8] = *(const uint4*)(g_Wl + go);
            }
#pragma unroll
            for (int i = 0; i < 2; i++) {
                int idx = t + i * 256;
                int row = idx >> 3, seg = idx & 7;
                size_t go = (size_t)(jt * 64 + row) * I_ + kc + seg * 8;
                *(uint4*)&Xh_s[row][seg * 8] = *(const uint4*)(g_xh + go);
                *(uint4*)&Xl_s[row][seg * 8] = *(const uint4*)(g_xl + go);
            }
        }
        __syncthreads();

#pragma unroll
        for (int kst = 0; kst < 4; kst++) {
            int k0 = kst * 16 + 2 * tig;
            uint32_t ah0 = *(uint32_t*)&Wh_s[w * 16 + g][k0];
            uint32_t ah1 = *(uint32_t*)&Wh_s[w * 16 + g + 8][k0];
            uint32_t ah2 = *(uint32_t*)&Wh_s[w * 16 + g][k0 + 8];
            uint32_t ah3 = *(uint32_t*)&Wh_s[w * 16 + g + 8][k0 + 8];
            uint32_t al0 = *(uint32_t*)&Wl_s[w * 16 + g][k0];
            uint32_t al1 = *(uint32_t*)&Wl_s[w * 16 + g + 8][k0];
            uint32_t al2 = *(uint32_t*)&Wl_s[w * 16 + g][k0 + 8];
            uint32_t al3 = *(uint32_t*)&Wl_s[w * 16 + g + 8][k0 + 8];

#pragma unroll
            for (int jf = 0; jf < 8; jf++) {
                uint32_t bh0 = *(uint32_t*)&Xh_s[jf * 8 + g][k0];
                uint32_t bh1 = *(uint32_t*)&Xh_s[jf * 8 + g][k0 + 8];
                uint32_t bl0 = *(uint32_t*)&Xl_s[jf * 8 + g][k0];
                uint32_t bl1 = *(uint32_t*)&Xl_s[jf * 8 + g][k0 + 8];
                mma_bf16(acc[jf], ah0, ah1, ah2, ah3, bh0, bh1);
                mma_bf16(acc[jf], al0, al1, al2, al3, bh0, bh1);
                mma_bf16(acc[jf], ah0, ah1, ah2, ah3, bl0, bl1);
            }
        }
    }

    // epilogue: h = clamp(fv*sc[m] + of[m], 0, 1)
    int m0 = mt * 128 + w * 16;
    float sc0 = g_sc[m0 + g],     of0 = g_of[m0 + g];
    float sc1 = g_sc[m0 + g + 8], of1 = g_of[m0 + g + 8];
#pragma unroll
    for (int jf = 0; jf < 8; jf++) {
        int j = jt * 64 + jf * 8 + 2 * tig;
        float h00 = fminf(fmaxf(acc[jf][0] * sc0 + of0, 0.0f), 1.0f);
        float h01 = fminf(fmaxf(acc[jf][1] * sc0 + of0, 0.0f), 1.0f);
        float h10 = fminf(fmaxf(acc[jf][2] * sc1 + of1, 0.0f), 1.0f);
        float h11 = fminf(fmaxf(acc[jf][3] * sc1 + of1, 0.0f), 1.0f);
        *(float2*)&g_Ht[(size_t)(m0 + g) * B_ + j]     = make_float2(h00, h01);
        *(float2*)&g_Ht[(size_t)(m0 + g + 8) * B_ + j] = make_float2(h10, h11);
    }
}

// ---------------------------------------------------------------------------
// Kernel C (tensor forest): h loaded directly (pipelined); no sc/of, no clamp.
// ---------------------------------------------------------------------------
__global__ void __launch_bounds__(256) k_forest(float* __restrict__ out) {
    __shared__ uint32_t resp_s[8][U_][72];

    int t    = threadIdx.x;
    int w    = t >> 5;
    int lane = t & 31;
    int g    = lane >> 2;
    int tig  = lane & 3;
    int bt   = blockIdx.x;   // 8 b-tiles of 128
    int ng   = blockIdx.y;   // 64 n-groups of 8

    {   // stage 8 response tiles
        const uint4* src = (const uint4*)(g_respP + (size_t)ng * 8 * (U_ * L_));
#pragma unroll
        for (int j = 0; j < 8; j++) {
            int idx = t + j * 256;
            uint4 v = src[idx];
            int fi = idx * 4;
            int row = fi >> 6, col = fi & 63;
            *(uint4*)&resp_s[row >> 4][row & 15][col] = v;
        }
    }

    float acc[2][4] = {};
    int b_r0 = bt * 128 + w * 16 + g;
    const float* hvb = g_Ht + (size_t)ng * 48 * B_;

    float hv[2][12];
#pragma unroll
    for (int d = 0; d < 6; d++) {
        hv[0][d]     = hvb[(size_t)d * B_ + b_r0];
        hv[0][6 + d] = hvb[(size_t)d * B_ + b_r0 + 8];
    }

    __syncthreads();

#pragma unroll
    for (int nl = 0; nl < 8; nl++) {
        int cur = nl & 1, nxt = cur ^ 1;

        if (nl < 7) {
            const float* hvn = hvb + (size_t)(nl + 1) * 6 * B_;
#pragma unroll
            for (int d = 0; d < 6; d++) {
                hv[nxt][d]     = hvn[(size_t)d * B_ + b_r0];
                hv[nxt][6 + d] = hvn[(size_t)d * B_ + b_r0 + 8];
            }
        }

        const float* h0 = &hv[cur][0];
        const float* h1 = &hv[cur][6];

        float f0a = (tig & 1) ? (1.0f - h0[0]) : h0[0];
        float f0b = (tig & 1) ? (1.0f - h1[0]) : h1[0];
        float f1a = (tig & 2) ? (1.0f - h0[1]) : h0[1];
        float f1b = (tig & 2) ? (1.0f - h1[1]) : h1[1];
        float F0 = f0a * f1a, F1 = f0b * f1b;
        float A00 = F0 * h0[2], A01 = F0 * (1.0f - h0[2]);
        float A10 = F1 * h1[2], A11 = F1 * (1.0f - h1[2]);

        float S0[8], S1[8];
        {
            float p0 = h0[3], p1 = 1.0f - h0[3];
            float r0 = h0[4], r1 = 1.0f - h0[4];
            float q0 = p0 * r0, q1 = p1 * r0, q2 = p0 * r1, q3 = p1 * r1;
            float t5 = h0[5], u5 = 1.0f - h0[5];
            S0[0] = q0 * t5; S0[1] = q1 * t5; S0[2] = q2 * t5; S0[3] = q3 * t5;
            S0[4] = q0 * u5; S0[5] = q1 * u5; S0[6] = q2 * u5; S0[7] = q3 * u5;
        }
        {
            float p0 = h1[3], p1 = 1.0f - h1[3];
            float r0 = h1[4], r1 = 1.0f - h1[4];
            float q0 = p0 * r0, q1 = p1 * r0, q2 = p0 * r1, q3 = p1 * r1;
            float t5 = h1[5], u5 = 1.0f - h1[5];
            S1[0] = q0 * t5; S1[1] = q1 * t5; S1[2] = q2 * t5; S1[3] = q3 * t5;
            S1[4] = q0 * u5; S1[5] = q1 * u5; S1[6] = q2 * u5; S1[7] = q3 * u5;
        }

#pragma unroll
        for (int s = 0; s < 8; s++) {
            uint32_t a0 = __float_as_uint(A00 * S0[s]);
            uint32_t a1 = __float_as_uint(A10 * S1[s]);
            uint32_t a2 = __float_as_uint(A01 * S0[s]);
            uint32_t a3 = __float_as_uint(A11 * S1[s]);
#pragma unroll
            for (int nr = 0; nr < 2; nr++) {
                uint2 bb = *(const uint2*)&resp_s[nl][nr * 8 + g][8 * s + 2 * tig];
                mma_tf32(acc[nr], a0, a1, a2, a3, bb.x, bb.y);
            }
        }
    }

#pragma unroll
    for (int nr = 0; nr < 2; nr++) {
        int u = nr * 8 + 2 * tig;
        atomicAdd(&out[b_r0 * U_ + u],           acc[nr][0]);
        atomicAdd(&out[b_r0 * U_ + u + 1],       acc[nr][1]);
        atomicAdd(&out[(b_r0 + 8) * U_ + u],     acc[nr][2]);
        atomicAdd(&out[(b_r0 + 8) * U_ + u + 1], acc[nr][3]);
    }
}

// ---------------------------------------------------------------------------
extern "C" void kernel_launch(void* const* d_in, const int* in_sizes, int n_in,
                              void* d_out, int out_size) {
    const float* x    = (const float*)d_in[0];  // [B, I]
    const float* fsl  = (const float*)d_in[1];  // [I, N, D]
    const float* th   = (const float*)d_in[2];  // [N, D]
    const float* lt   = (const float*)d_in[3];  // [N, D]
    const float* resp = (const float*)d_in[4];  // [N, U, 2^D]
    float* out = (float*)d_out;                 // [B, U]

    cudaMemsetAsync(out, 0, (size_t)B_ * U_ * sizeof(float), 0);

    k_prep<<<512, 256>>>(fsl, x, th, lt, resp);
    k_gemm<<<dim3(B_ / 64, ND_ / 128), 256>>>();
    k_forest<<<dim3(B_ / 128, N_ / 8), 256>>>(out);
}

// round 15
// speedup vs baseline: 1.0477x; 1.0477x over previous
#include <cuda_runtime.h>
#include <cuda_bf16.h>
#include <cstdint>

#define B_  1024
#define I_  256
#define N_  512
#define D_  6
#define U_  16
#define L_  64
#define ND_ (N_ * D_)   // 3072

__device__ __nv_bfloat16 g_Wh[ND_ * I_];     // W transposed hi, [m][k]
__device__ __nv_bfloat16 g_Wl[ND_ * I_];     // W transposed lo, [m][k]
__device__ __nv_bfloat16 g_xh[B_ * I_];      // x hi, [j][k]
__device__ __nv_bfloat16 g_xl[B_ * I_];      // x lo, [j][k]
__device__ float g_Ht[ND_ * B_];             // sparsemoid bins h, [m][j]
__device__ float g_sc [ND_];                 // 0.5*exp(-lt)
__device__ float g_of [ND_];                 // 0.5 - th*0.5*exp(-lt)
__device__ uint32_t g_respP[N_ * U_ * L_];   // resp, tf32 bits, pair-interleaved

__device__ __forceinline__ uint32_t tf32r(float x) {
    uint32_t r; asm("cvt.rna.tf32.f32 %0, %1;" : "=r"(r) : "f"(x)); return r;
}

__device__ __forceinline__ void mma_tf32(float c[4], uint32_t a0, uint32_t a1,
                                         uint32_t a2, uint32_t a3,
                                         uint32_t b0, uint32_t b1) {
    asm volatile(
        "mma.sync.aligned.m16n8k8.row.col.f32.tf32.tf32.f32 "
        "{%0,%1,%2,%3}, {%4,%5,%6,%7}, {%8,%9}, {%0,%1,%2,%3};"
        : "+f"(c[0]), "+f"(c[1]), "+f"(c[2]), "+f"(c[3])
        : "r"(a0), "r"(a1), "r"(a2), "r"(a3), "r"(b0), "r"(b1));
}

__device__ __forceinline__ void mma_bf16(float c[4], uint32_t a0, uint32_t a1,
                                         uint32_t a2, uint32_t a3,
                                         uint32_t b0, uint32_t b1) {
    asm volatile(
        "mma.sync.aligned.m16n8k16.row.col.f32.bf16.bf16.f32 "
        "{%0,%1,%2,%3}, {%4,%5,%6,%7}, {%8,%9}, {%0,%1,%2,%3};"
        : "+f"(c[0]), "+f"(c[1]), "+f"(c[2]), "+f"(c[3])
        : "r"(a0), "r"(a1), "r"(a2), "r"(a3), "r"(b0), "r"(b1));
}

// ---------------------------------------------------------------------------
// Kernel P: prep (sparsemax -> bf16 W transpose, x split, sc/of). 512 x 256.
// (resp conversion moved into k_gemm prologue)
// ---------------------------------------------------------------------------
__global__ void __launch_bounds__(256) k_prep(const float* __restrict__ fsl,
                                              const float* __restrict__ x,
                                              const float* __restrict__ th,
                                              const float* __restrict__ lt) {
    __shared__ float fsm[48][33];   // [m_local][i_local]

    int t   = threadIdx.x;
    int bid = blockIdx.x;
    int gt  = bid * 256 + t;

    // ---- sparsemax for (i, n) = (it*32+li, nt*8+ln) ----
    int it = bid >> 6;       // 0..7
    int nt = bid & 63;       // 0..63
    int li = t >> 3, ln = t & 7;
    {
        const float2* z2 = (const float2*)(fsl + ((size_t)(it * 32 + li) * N_ + nt * 8 + ln) * D_);
        float2 za = z2[0], zb = z2[1], zc = z2[2];
        float z0 = za.x, z1 = za.y, z2v = zb.x, z3 = zb.y, z4 = zc.x, z5 = zc.y;
        float s0 = z0, s1 = z1, s2 = z2v, s3 = z3, s4 = z4, s5 = z5;
#define CSWP(a, b) { float _mx = fmaxf(a, b); float _mn = fminf(a, b); a = _mx; b = _mn; }
        CSWP(s1, s2) CSWP(s4, s5) CSWP(s0, s2) CSWP(s3, s5)
        CSWP(s0, s1) CSWP(s3, s4) CSWP(s2, s5) CSWP(s0, s3)
        CSWP(s1, s4) CSWP(s2, s4) CSWP(s1, s3) CSWP(s2, s3)
#undef CSWP
        float cs = s0; int k = 1; float ts = cs;
        cs += s1; if (1.0f + 2.0f * s1 > cs) { k = 2; ts = cs; }
        cs += s2; if (1.0f + 3.0f * s2 > cs) { k = 3; ts = cs; }
        cs += s3; if (1.0f + 4.0f * s3 > cs) { k = 4; ts = cs; }
        cs += s4; if (1.0f + 5.0f * s4 > cs) { k = 5; ts = cs; }
        cs += s5; if (1.0f + 6.0f * s5 > cs) { k = 6; ts = cs; }
        float tau = (ts - 1.0f) / (float)k;

        fsm[ln * 6 + 0][li] = fmaxf(z0 - tau, 0.0f);
        fsm[ln * 6 + 1][li] = fmaxf(z1 - tau, 0.0f);
        fsm[ln * 6 + 2][li] = fmaxf(z2v - tau, 0.0f);
        fsm[ln * 6 + 3][li] = fmaxf(z3 - tau, 0.0f);
        fsm[ln * 6 + 4][li] = fmaxf(z4 - tau, 0.0f);
        fsm[ln * 6 + 5][li] = fmaxf(z5 - tau, 0.0f);
    }

    if (gt < (B_ * I_) / 4) {   // x split
        float4 v = ((const float4*)x)[gt];
        float f[4] = { v.x, v.y, v.z, v.w };
        __nv_bfloat16 h[4], l[4];
#pragma unroll
        for (int i = 0; i < 4; i++) {
            h[i] = __float2bfloat16_rn(f[i]);
            l[i] = __float2bfloat16_rn(f[i] - __bfloat162float(h[i]));
        }
        __nv_bfloat162 h01(h[0], h[1]), h23(h[2], h[3]);
        __nv_bfloat162 l01(l[0], l[1]), l23(l[2], l[3]);
        uint2 uh = make_uint2(*reinterpret_cast<uint32_t*>(&h01),
                              *reinterpret_cast<uint32_t*>(&h23));
        uint2 ul = make_uint2(*reinterpret_cast<uint32_t*>(&l01),
                              *reinterpret_cast<uint32_t*>(&l23));
        *(uint2*)(g_xh + (size_t)gt * 4) = uh;
        *(uint2*)(g_xl + (size_t)gt * 4) = ul;
    }

    if (gt < ND_) {   // scale/offset
        float s = 0.5f * expf(-lt[gt]);
        g_sc[gt] = s;
        g_of[gt] = 0.5f - th[gt] * s;
    }

    // ---- emit transposed bf16 W: rows m = nt*48 + r, cols k = it*32 + lane ----
    __syncthreads();
    {
        int w = t >> 5, lane = t & 31;
#pragma unroll
        for (int r2 = 0; r2 < 6; r2++) {
            int r = w * 6 + r2;
            float v = fsm[r][lane];
            __nv_bfloat16 hi = __float2bfloat16_rn(v);
            __nv_bfloat16 lo = __float2bfloat16_rn(v - __bfloat162float(hi));
            size_t o = (size_t)(nt * 48 + r) * I_ + it * 32 + lane;
            g_Wh[o] = hi;
            g_Wl[o] = lo;
        }
    }
}

// ---------------------------------------------------------------------------
// Kernel B: tensor GEMM + sparsemoid epilogue -> g_Ht.
// Prologue additionally converts resp -> tf32 pair-interleaved (overlaps
// with first tile staging; independent of W/x).
// ---------------------------------------------------------------------------
__global__ void __launch_bounds__(256) k_gemm(const float* __restrict__ resp) {
    __shared__ __nv_bfloat16 Wh_s[128][72], Wl_s[128][72];
    __shared__ __nv_bfloat16 Xh_s[64][72],  Xl_s[64][72];

    int t    = threadIdx.x;
    int w    = t >> 5;
    int lane = t & 31;
    int g    = lane >> 2;
    int tig  = lane & 3;
    int jt   = blockIdx.x;   // 16
    int mt   = blockIdx.y;   // 24

    // ---- resp -> tf32 pair-interleaved (distributed over 98304 threads) ----
    {
        int base = (mt * 16 + jt) * 256 + t;          // 0..98303
#pragma unroll
        for (int itc = 0; itc < 2; itc++) {
            int gt = base + itc * (16 * 24 * 256);
            if (gt < (N_ * U_ * L_) / 4) {
                int fi = gt * 4;
                int nu = fi >> 6;
                int cc = (fi & 63) >> 2;
                int s = cc >> 1, half = cc & 1;
                const float* r = resp + (size_t)nu * 64 + 8 * s + 2 * half;
                float2 ra = *(const float2*)(r);
                float2 rb = *(const float2*)(r + 4);
                uint4 o;
                o.x = tf32r(ra.x);
                o.y = tf32r(rb.x);
                o.z = tf32r(ra.y);
                o.w = tf32r(rb.y);
                *(uint4*)(g_respP + fi) = o;
            }
        }
    }

    float acc[8][4];
#pragma unroll
    for (int jf = 0; jf < 8; jf++)
#pragma unroll
        for (int i = 0; i < 4; i++) acc[jf][i] = 0.0f;

    for (int kc = 0; kc < I_; kc += 64) {
        __syncthreads();
        {
#pragma unroll
            for (int i = 0; i < 4; i++) {
                int idx = t + i * 256;
                int row = idx >> 3, seg = idx & 7;
                size_t go = (size_t)(mt * 128 + row) * I_ + kc + seg * 8;
                *(uint4*)&Wh_s[row][seg * 8] = *(const uint4*)(g_Wh + go);
                *(uint4*)&Wl_s[row][seg * 8] = *(const uint4*)(g_Wl + go);
            }
#pragma unroll
            for (int i = 0; i < 2; i++) {
                int idx = t + i * 256;
                int row = idx >> 3, seg = idx & 7;
                size_t go = (size_t)(jt * 64 + row) * I_ + kc + seg * 8;
                *(uint4*)&Xh_s[row][seg * 8] = *(const uint4*)(g_xh + go);
                *(uint4*)&Xl_s[row][seg * 8] = *(const uint4*)(g_xl + go);
            }
        }
        __syncthreads();

#pragma unroll
        for (int kst = 0; kst < 4; kst++) {
            int k0 = kst * 16 + 2 * tig;
            uint32_t ah0 = *(uint32_t*)&Wh_s[w * 16 + g][k0];
            uint32_t ah1 = *(uint32_t*)&Wh_s[w * 16 + g + 8][k0];
            uint32_t ah2 = *(uint32_t*)&Wh_s[w * 16 + g][k0 + 8];
            uint32_t ah3 = *(uint32_t*)&Wh_s[w * 16 + g + 8][k0 + 8];
            uint32_t al0 = *(uint32_t*)&Wl_s[w * 16 + g][k0];
            uint32_t al1 = *(uint32_t*)&Wl_s[w * 16 + g + 8][k0];
            uint32_t al2 = *(uint32_t*)&Wl_s[w * 16 + g][k0 + 8];
            uint32_t al3 = *(uint32_t*)&Wl_s[w * 16 + g + 8][k0 + 8];

#pragma unroll
            for (int jf = 0; jf < 8; jf++) {
                uint32_t bh0 = *(uint32_t*)&Xh_s[jf * 8 + g][k0];
                uint32_t bh1 = *(uint32_t*)&Xh_s[jf * 8 + g][k0 + 8];
                uint32_t bl0 = *(uint32_t*)&Xl_s[jf * 8 + g][k0];
                uint32_t bl1 = *(uint32_t*)&Xl_s[jf * 8 + g][k0 + 8];
                mma_bf16(acc[jf], ah0, ah1, ah2, ah3, bh0, bh1);
                mma_bf16(acc[jf], al0, al1, al2, al3, bh0, bh1);
                mma_bf16(acc[jf], ah0, ah1, ah2, ah3, bl0, bl1);
            }
        }
    }

    // epilogue: h = clamp(fv*sc[m] + of[m], 0, 1)
    int m0 = mt * 128 + w * 16;
    float sc0 = g_sc[m0 + g],     of0 = g_of[m0 + g];
    float sc1 = g_sc[m0 + g + 8], of1 = g_of[m0 + g + 8];
#pragma unroll
    for (int jf = 0; jf < 8; jf++) {
        int j = jt * 64 + jf * 8 + 2 * tig;
        float h00 = fminf(fmaxf(acc[jf][0] * sc0 + of0, 0.0f), 1.0f);
        float h01 = fminf(fmaxf(acc[jf][1] * sc0 + of0, 0.0f), 1.0f);
        float h10 = fminf(fmaxf(acc[jf][2] * sc1 + of1, 0.0f), 1.0f);
        float h11 = fminf(fmaxf(acc[jf][3] * sc1 + of1, 0.0f), 1.0f);
        *(float2*)&g_Ht[(size_t)(m0 + g) * B_ + j]     = make_float2(h00, h01);
        *(float2*)&g_Ht[(size_t)(m0 + g + 8) * B_ + j] = make_float2(h10, h11);
    }
}

// ---------------------------------------------------------------------------
// Kernel C (tensor forest): n-group of 4 -> 1024 blocks for occupancy.
// Grid (8 b-tiles of 128, 128 n-groups of 4), 256 threads, 4 blocks/SM.
// ---------------------------------------------------------------------------
__global__ void __launch_bounds__(256, 4) k_forest(float* __restrict__ out) {
    __shared__ uint32_t resp_s[4][U_][72];

    int t    = threadIdx.x;
    int w    = t >> 5;
    int lane = t & 31;
    int g    = lane >> 2;
    int tig  = lane & 3;
    int bt   = blockIdx.x;   // 8 b-tiles of 128
    int ng   = blockIdx.y;   // 128 n-groups of 4

    {   // stage 4 response tiles: 4096 words, 1024 uint4, 4 per thread
        const uint4* src = (const uint4*)(g_respP + (size_t)ng * 4 * (U_ * L_));
#pragma unroll
        for (int j = 0; j < 4; j++) {
            int idx = t + j * 256;
            uint4 v = src[idx];
            int fi = idx * 4;
            int row = fi >> 6, col = fi & 63;
            *(uint4*)&resp_s[row >> 4][row & 15][col] = v;
        }
    }

    float acc[2][4] = {};
    int b_r0 = bt * 128 + w * 16 + g;
    const float* hvb = g_Ht + (size_t)ng * 24 * B_;

    float hv[2][12];
#pragma unroll
    for (int d = 0; d < 6; d++) {
        hv[0][d]     = hvb[(size_t)d * B_ + b_r0];
        hv[0][6 + d] = hvb[(size_t)d * B_ + b_r0 + 8];
    }

    __syncthreads();

#pragma unroll
    for (int nl = 0; nl < 4; nl++) {
        int cur = nl & 1, nxt = cur ^ 1;

        if (nl < 3) {
            const float* hvn = hvb + (size_t)(nl + 1) * 6 * B_;
#pragma unroll
            for (int d = 0; d < 6; d++) {
                hv[nxt][d]     = hvn[(size_t)d * B_ + b_r0];
                hv[nxt][6 + d] = hvn[(size_t)d * B_ + b_r0 + 8];
            }
        }

        const float* h0 = &hv[cur][0];
        const float* h1 = &hv[cur][6];

        float f0a = (tig & 1) ? (1.0f - h0[0]) : h0[0];
        float f0b = (tig & 1) ? (1.0f - h1[0]) : h1[0];
        float f1a = (tig & 2) ? (1.0f - h0[1]) : h0[1];
        float f1b = (tig & 2) ? (1.0f - h1[1]) : h1[1];
        float F0 = f0a * f1a, F1 = f0b * f1b;
        float A00 = F0 * h0[2], A01 = F0 * (1.0f - h0[2]);
        float A10 = F1 * h1[2], A11 = F1 * (1.0f - h1[2]);

        float S0[8], S1[8];
        {
            float p0 = h0[3], p1 = 1.0f - h0[3];
            float r0 = h0[4], r1 = 1.0f - h0[4];
            float q0 = p0 * r0, q1 = p1 * r0, q2 = p0 * r1, q3 = p1 * r1;
            float t5 = h0[5], u5 = 1.0f - h0[5];
            S0[0] = q0 * t5; S0[1] = q1 * t5; S0[2] = q2 * t5; S0[3] = q3 * t5;
            S0[4] = q0 * u5; S0[5] = q1 * u5; S0[6] = q2 * u5; S0[7] = q3 * u5;
        }
        {
            float p0 = h1[3], p1 = 1.0f - h1[3];
            float r0 = h1[4], r1 = 1.0f - h1[4];
            float q0 = p0 * r0, q1 = p1 * r0, q2 = p0 * r1, q3 = p1 * r1;
            float t5 = h1[5], u5 = 1.0f - h1[5];
            S1[0] = q0 * t5; S1[1] = q1 * t5; S1[2] = q2 * t5; S1[3] = q3 * t5;
            S1[4] = q0 * u5; S1[5] = q1 * u5; S1[6] = q2 * u5; S1[7] = q3 * u5;
        }

#pragma unroll
        for (int s = 0; s < 8; s++) {
            uint32_t a0 = __float_as_uint(A00 * S0[s]);
            uint32_t a1 = __float_as_uint(A10 * S1[s]);
            uint32_t a2 = __float_as_uint(A01 * S0[s]);
            uint32_t a3 = __float_as_uint(A11 * S1[s]);
#pragma unroll
            for (int nr = 0; nr < 2; nr++) {
                uint2 bb = *(const uint2*)&resp_s[nl][nr * 8 + g][8 * s + 2 * tig];
                mma_tf32(acc[nr], a0, a1, a2, a3, bb.x, bb.y);
            }
        }
    }

#pragma unroll
    for (int nr = 0; nr < 2; nr++) {
        int u = nr * 8 + 2 * tig;
        atomicAdd(&out[b_r0 * U_ + u],           acc[nr][0]);
        atomicAdd(&out[b_r0 * U_ + u + 1],       acc[nr][1]);
        atomicAdd(&out[(b_r0 + 8) * U_ + u],     acc[nr][2]);
        atomicAdd(&out[(b_r0 + 8) * U_ + u + 1], acc[nr][3]);
    }
}

// ---------------------------------------------------------------------------
extern "C" void kernel_launch(void* const* d_in, const int* in_sizes, int n_in,
                              void* d_out, int out_size) {
    const float* x    = (const float*)d_in[0];  // [B, I]
    const float* fsl  = (const float*)d_in[1];  // [I, N, D]
    const float* th   = (const float*)d_in[2];  // [N, D]
    const float* lt   = (const float*)d_in[3];  // [N, D]
    const float* resp = (const float*)d_in[4];  // [N, U, 2^D]
    float* out = (float*)d_out;                 // [B, U]

    cudaMemsetAsync(out, 0, (size_t)B_ * U_ * sizeof(float), 0);

    k_prep<<<512, 256>>>(fsl, x, th, lt);
    k_gemm<<<dim3(B_ / 64, ND_ / 128), 256>>>(resp);
    k_forest<<<dim3(B_ / 128, N_ / 4), 256>>>(out);
}

// round 16
// speedup vs baseline: 1.0539x; 1.0060x over previous
#include <cuda_runtime.h>
#include <cuda_bf16.h>
#include <cstdint>

#define B_  1024
#define I_  256
#define N_  512
#define D_  6
#define U_  16
#define L_  64
#define ND_ (N_ * D_)   // 3072

__device__ __nv_bfloat16 g_Wh[ND_ * I_];     // W transposed hi, [m][k]
__device__ __nv_bfloat16 g_Wl[ND_ * I_];     // W transposed lo, [m][k]
__device__ __nv_bfloat16 g_xh[B_ * I_];      // x hi, [j][k]
__device__ __nv_bfloat16 g_xl[B_ * I_];      // x lo, [j][k]
__device__ float g_Ht[ND_ * B_];             // sparsemoid bins h, [m][j]
__device__ uint32_t g_respP[N_ * U_ * L_];   // resp, tf32 bits, pair-interleaved

__device__ __forceinline__ uint32_t tf32r(float x) {
    uint32_t r; asm("cvt.rna.tf32.f32 %0, %1;" : "=r"(r) : "f"(x)); return r;
}

__device__ __forceinline__ void mma_tf32(float c[4], uint32_t a0, uint32_t a1,
                                         uint32_t a2, uint32_t a3,
                                         uint32_t b0, uint32_t b1) {
    asm volatile(
        "mma.sync.aligned.m16n8k8.row.col.f32.tf32.tf32.f32 "
        "{%0,%1,%2,%3}, {%4,%5,%6,%7}, {%8,%9}, {%0,%1,%2,%3};"
        : "+f"(c[0]), "+f"(c[1]), "+f"(c[2]), "+f"(c[3])
        : "r"(a0), "r"(a1), "r"(a2), "r"(a3), "r"(b0), "r"(b1));
}

__device__ __forceinline__ void mma_bf16(float c[4], uint32_t a0, uint32_t a1,
                                         uint32_t a2, uint32_t a3,
                                         uint32_t b0, uint32_t b1) {
    asm volatile(
        "mma.sync.aligned.m16n8k16.row.col.f32.bf16.bf16.f32 "
        "{%0,%1,%2,%3}, {%4,%5,%6,%7}, {%8,%9}, {%0,%1,%2,%3};"
        : "+f"(c[0]), "+f"(c[1]), "+f"(c[2]), "+f"(c[3])
        : "r"(a0), "r"(a1), "r"(a2), "r"(a3), "r"(b0), "r"(b1));
}

// ---------------------------------------------------------------------------
// Kernel P: prep (sparsemax -> bf16 W transpose, x split, out zeroing).
// 512 x 256. sc/of moved into gemm epilogue; memset replaced by out zeroing.
// ---------------------------------------------------------------------------
__global__ void __launch_bounds__(256) k_prep(const float* __restrict__ fsl,
                                              const float* __restrict__ x,
                                              float* __restrict__ out) {
    __shared__ float fsm[48][33];   // [m_local][i_local]

    int t   = threadIdx.x;
    int bid = blockIdx.x;
    int gt  = bid * 256 + t;

    // ---- sparsemax for (i, n) = (it*32+li, nt*8+ln) ----
    int it = bid >> 6;       // 0..7
    int nt = bid & 63;       // 0..63
    int li = t >> 3, ln = t & 7;
    {
        const float2* z2 = (const float2*)(fsl + ((size_t)(it * 32 + li) * N_ + nt * 8 + ln) * D_);
        float2 za = z2[0], zb = z2[1], zc = z2[2];
        float z0 = za.x, z1 = za.y, z2v = zb.x, z3 = zb.y, z4 = zc.x, z5 = zc.y;
        float s0 = z0, s1 = z1, s2 = z2v, s3 = z3, s4 = z4, s5 = z5;
#define CSWP(a, b) { float _mx = fmaxf(a, b); float _mn = fminf(a, b); a = _mx; b = _mn; }
        CSWP(s1, s2) CSWP(s4, s5) CSWP(s0, s2) CSWP(s3, s5)
        CSWP(s0, s1) CSWP(s3, s4) CSWP(s2, s5) CSWP(s0, s3)
        CSWP(s1, s4) CSWP(s2, s4) CSWP(s1, s3) CSWP(s2, s3)
#undef CSWP
        float cs = s0; int k = 1; float ts = cs;
        cs += s1; if (1.0f + 2.0f * s1 > cs) { k = 2; ts = cs; }
        cs += s2; if (1.0f + 3.0f * s2 > cs) { k = 3; ts = cs; }
        cs += s3; if (1.0f + 4.0f * s3 > cs) { k = 4; ts = cs; }
        cs += s4; if (1.0f + 5.0f * s4 > cs) { k = 5; ts = cs; }
        cs += s5; if (1.0f + 6.0f * s5 > cs) { k = 6; ts = cs; }
        float tau = (ts - 1.0f) / (float)k;

        fsm[ln * 6 + 0][li] = fmaxf(z0 - tau, 0.0f);
        fsm[ln * 6 + 1][li] = fmaxf(z1 - tau, 0.0f);
        fsm[ln * 6 + 2][li] = fmaxf(z2v - tau, 0.0f);
        fsm[ln * 6 + 3][li] = fmaxf(z3 - tau, 0.0f);
        fsm[ln * 6 + 4][li] = fmaxf(z4 - tau, 0.0f);
        fsm[ln * 6 + 5][li] = fmaxf(z5 - tau, 0.0f);
    }

    if (gt < (B_ * I_) / 4) {   // x split
        float4 v = ((const float4*)x)[gt];
        float f[4] = { v.x, v.y, v.z, v.w };
        __nv_bfloat16 h[4], l[4];
#pragma unroll
        for (int i = 0; i < 4; i++) {
            h[i] = __float2bfloat16_rn(f[i]);
            l[i] = __float2bfloat16_rn(f[i] - __bfloat162float(h[i]));
        }
        __nv_bfloat162 h01(h[0], h[1]), h23(h[2], h[3]);
        __nv_bfloat162 l01(l[0], l[1]), l23(l[2], l[3]);
        uint2 uh = make_uint2(*reinterpret_cast<uint32_t*>(&h01),
                              *reinterpret_cast<uint32_t*>(&h23));
        uint2 ul = make_uint2(*reinterpret_cast<uint32_t*>(&l01),
                              *reinterpret_cast<uint32_t*>(&l23));
        *(uint2*)(g_xh + (size_t)gt * 4) = uh;
        *(uint2*)(g_xl + (size_t)gt * 4) = ul;
    }

    if (gt < (B_ * U_) / 4) {   // zero the output buffer (poisoned by harness)
        ((float4*)out)[gt] = make_float4(0.0f, 0.0f, 0.0f, 0.0f);
    }

    // ---- emit transposed bf16 W, paired 32-bit stores ----
    __syncthreads();
    {
        // 48 rows x 16 col-pairs = 768 items, 3 per thread
#pragma unroll
        for (int i = 0; i < 3; i++) {
            int idx = t + i * 256;
            int r = idx >> 4, c2 = (idx & 15) * 2;
            float v0 = fsm[r][c2], v1 = fsm[r][c2 + 1];
            __nv_bfloat16 h0 = __float2bfloat16_rn(v0);
            __nv_bfloat16 l0 = __float2bfloat16_rn(v0 - __bfloat162float(h0));
            __nv_bfloat16 h1 = __float2bfloat16_rn(v1);
            __nv_bfloat16 l1 = __float2bfloat16_rn(v1 - __bfloat162float(h1));
            __nv_bfloat162 hp(h0, h1), lp(l0, l1);
            size_t o = (size_t)(nt * 48 + r) * I_ + it * 32 + c2;
            *(uint32_t*)(g_Wh + o) = *reinterpret_cast<uint32_t*>(&hp);
            *(uint32_t*)(g_Wl + o) = *reinterpret_cast<uint32_t*>(&lp);
        }
    }
}

// ---------------------------------------------------------------------------
// Kernel B: tensor GEMM + sparsemoid epilogue -> g_Ht.
// Prologue converts resp -> tf32 pair-interleaved; sc/of computed in-place.
// ---------------------------------------------------------------------------
__global__ void __launch_bounds__(256) k_gemm(const float* __restrict__ resp,
                                              const float* __restrict__ th,
                                              const float* __restrict__ lt) {
    __shared__ __nv_bfloat16 Wh_s[128][72], Wl_s[128][72];
    __shared__ __nv_bfloat16 Xh_s[64][72],  Xl_s[64][72];

    int t    = threadIdx.x;
    int w    = t >> 5;
    int lane = t & 31;
    int g    = lane >> 2;
    int tig  = lane & 3;
    int jt   = blockIdx.x;   // 16
    int mt   = blockIdx.y;   // 24

    // sc/of for this thread's two m-rows (hidden behind K-loop)
    int m0 = mt * 128 + w * 16;
    float sc0 = 0.5f * expf(-lt[m0 + g]);
    float of0 = 0.5f - th[m0 + g] * sc0;
    float sc1 = 0.5f * expf(-lt[m0 + g + 8]);
    float of1 = 0.5f - th[m0 + g + 8] * sc1;

    // ---- resp -> tf32 pair-interleaved (distributed over 98304 threads) ----
    {
        int base = (mt * 16 + jt) * 256 + t;          // 0..98303
#pragma unroll
        for (int itc = 0; itc < 2; itc++) {
            int gt = base + itc * (16 * 24 * 256);
            if (gt < (N_ * U_ * L_) / 4) {
                int fi = gt * 4;
                int nu = fi >> 6;
                int cc = (fi & 63) >> 2;
                int s = cc >> 1, half = cc & 1;
                const float* r = resp + (size_t)nu * 64 + 8 * s + 2 * half;
                float2 ra = *(const float2*)(r);
                float2 rb = *(const float2*)(r + 4);
                uint4 o;
                o.x = tf32r(ra.x);
                o.y = tf32r(rb.x);
                o.z = tf32r(ra.y);
                o.w = tf32r(rb.y);
                *(uint4*)(g_respP + fi) = o;
            }
        }
    }

    float acc[8][4];
#pragma unroll
    for (int jf = 0; jf < 8; jf++)
#pragma unroll
        for (int i = 0; i < 4; i++) acc[jf][i] = 0.0f;

    for (int kc = 0; kc < I_; kc += 64) {
        __syncthreads();
        {
#pragma unroll
            for (int i = 0; i < 4; i++) {
                int idx = t + i * 256;
                int row = idx >> 3, seg = idx & 7;
                size_t go = (size_t)(mt * 128 + row) * I_ + kc + seg * 8;
                *(uint4*)&Wh_s[row][seg * 8] = *(const uint4*)(g_Wh + go);
                *(uint4*)&Wl_s[row][seg * 8] = *(const uint4*)(g_Wl + go);
            }
#pragma unroll
            for (int i = 0; i < 2; i++) {
                int idx = t + i * 256;
                int row = idx >> 3, seg = idx & 7;
                size_t go = (size_t)(jt * 64 + row) * I_ + kc + seg * 8;
                *(uint4*)&Xh_s[row][seg * 8] = *(const uint4*)(g_xh + go);
                *(uint4*)&Xl_s[row][seg * 8] = *(const uint4*)(g_xl + go);
            }
        }
        __syncthreads();

#pragma unroll
        for (int kst = 0; kst < 4; kst++) {
            int k0 = kst * 16 + 2 * tig;
            uint32_t ah0 = *(uint32_t*)&Wh_s[w * 16 + g][k0];
            uint32_t ah1 = *(uint32_t*)&Wh_s[w * 16 + g + 8][k0];
            uint32_t ah2 = *(uint32_t*)&Wh_s[w * 16 + g][k0 + 8];
            uint32_t ah3 = *(uint32_t*)&Wh_s[w * 16 + g + 8][k0 + 8];
            uint32_t al0 = *(uint32_t*)&Wl_s[w * 16 + g][k0];
            uint32_t al1 = *(uint32_t*)&Wl_s[w * 16 + g + 8][k0];
            uint32_t al2 = *(uint32_t*)&Wl_s[w * 16 + g][k0 + 8];
            uint32_t al3 = *(uint32_t*)&Wl_s[w * 16 + g + 8][k0 + 8];

#pragma unroll
            for (int jf = 0; jf < 8; jf++) {
                uint32_t bh0 = *(uint32_t*)&Xh_s[jf * 8 + g][k0];
                uint32_t bh1 = *(uint32_t*)&Xh_s[jf * 8 + g][k0 + 8];
                uint32_t bl0 = *(uint32_t*)&Xl_s[jf * 8 + g][k0];
                uint32_t bl1 = *(uint32_t*)&Xl_s[jf * 8 + g][k0 + 8];
                mma_bf16(acc[jf], ah0, ah1, ah2, ah3, bh0, bh1);
                mma_bf16(acc[jf], al0, al1, al2, al3, bh0, bh1);
                mma_bf16(acc[jf], ah0, ah1, ah2, ah3, bl0, bl1);
            }
        }
    }

    // epilogue: h = clamp(fv*sc[m] + of[m], 0, 1)
#pragma unroll
    for (int jf = 0; jf < 8; jf++) {
        int j = jt * 64 + jf * 8 + 2 * tig;
        float h00 = fminf(fmaxf(acc[jf][0] * sc0 + of0, 0.0f), 1.0f);
        float h01 = fminf(fmaxf(acc[jf][1] * sc0 + of0, 0.0f), 1.0f);
        float h10 = fminf(fmaxf(acc[jf][2] * sc1 + of1, 0.0f), 1.0f);
        float h11 = fminf(fmaxf(acc[jf][3] * sc1 + of1, 0.0f), 1.0f);
        *(float2*)&g_Ht[(size_t)(m0 + g) * B_ + j]     = make_float2(h00, h01);
        *(float2*)&g_Ht[(size_t)(m0 + g + 8) * B_ + j] = make_float2(h10, h11);
    }
}

// ---------------------------------------------------------------------------
// Kernel C (tensor forest, unchanged from R15): 1024 blocks, 4/SM.
// ---------------------------------------------------------------------------
__global__ void __launch_bounds__(256, 4) k_forest(float* __restrict__ out) {
    __shared__ uint32_t resp_s[4][U_][72];

    int t    = threadIdx.x;
    int w    = t >> 5;
    int lane = t & 31;
    int g    = lane >> 2;
    int tig  = lane & 3;
    int bt   = blockIdx.x;   // 8 b-tiles of 128
    int ng   = blockIdx.y;   // 128 n-groups of 4

    {   // stage 4 response tiles
        const uint4* src = (const uint4*)(g_respP + (size_t)ng * 4 * (U_ * L_));
#pragma unroll
        for (int j = 0; j < 4; j++) {
            int idx = t + j * 256;
            uint4 v = src[idx];
            int fi = idx * 4;
            int row = fi >> 6, col = fi & 63;
            *(uint4*)&resp_s[row >> 4][row & 15][col] = v;
        }
    }

    float acc[2][4] = {};
    int b_r0 = bt * 128 + w * 16 + g;
    const float* hvb = g_Ht + (size_t)ng * 24 * B_;

    float hv[2][12];
#pragma unroll
    for (int d = 0; d < 6; d++) {
        hv[0][d]     = hvb[(size_t)d * B_ + b_r0];
        hv[0][6 + d] = hvb[(size_t)d * B_ + b_r0 + 8];
    }

    __syncthreads();

#pragma unroll
    for (int nl = 0; nl < 4; nl++) {
        int cur = nl & 1, nxt = cur ^ 1;

        if (nl < 3) {
            const float* hvn = hvb + (size_t)(nl + 1) * 6 * B_;
#pragma unroll
            for (int d = 0; d < 6; d++) {
                hv[nxt][d]     = hvn[(size_t)d * B_ + b_r0];
                hv[nxt][6 + d] = hvn[(size_t)d * B_ + b_r0 + 8];
            }
        }

        const float* h0 = &hv[cur][0];
        const float* h1 = &hv[cur][6];

        float f0a = (tig & 1) ? (1.0f - h0[0]) : h0[0];
        float f0b = (tig & 1) ? (1.0f - h1[0]) : h1[0];
        float f1a = (tig & 2) ? (1.0f - h0[1]) : h0[1];
        float f1b = (tig & 2) ? (1.0f - h1[1]) : h1[1];
        float F0 = f0a * f1a, F1 = f0b * f1b;
        float A00 = F0 * h0[2], A01 = F0 * (1.0f - h0[2]);
        float A10 = F1 * h1[2], A11 = F1 * (1.0f - h1[2]);

        float S0[8], S1[8];
        {
            float p0 = h0[3], p1 = 1.0f - h0[3];
            float r0 = h0[4], r1 = 1.0f - h0[4];
            float q0 = p0 * r0, q1 = p1 * r0, q2 = p0 * r1, q3 = p1 * r1;
            float t5 = h0[5], u5 = 1.0f - h0[5];
            S0[0] = q0 * t5; S0[1] = q1 * t5; S0[2] = q2 * t5; S0[3] = q3 * t5;
            S0[4] = q0 * u5; S0[5] = q1 * u5; S0[6] = q2 * u5; S0[7] = q3 * u5;
        }
        {
            float p0 = h1[3], p1 = 1.0f - h1[3];
            float r0 = h1[4], r1 = 1.0f - h1[4];
            float q0 = p0 * r0, q1 = p1 * r0, q2 = p0 * r1, q3 = p1 * r1;
            float t5 = h1[5], u5 = 1.0f - h1[5];
            S1[0] = q0 * t5; S1[1] = q1 * t5; S1[2] = q2 * t5; S1[3] = q3 * t5;
            S1[4] = q0 * u5; S1[5] = q1 * u5; S1[6] = q2 * u5; S1[7] = q3 * u5;
        }

#pragma unroll
        for (int s = 0; s < 8; s++) {
            uint32_t a0 = __float_as_uint(A00 * S0[s]);
            uint32_t a1 = __float_as_uint(A10 * S1[s]);
            uint32_t a2 = __float_as_uint(A01 * S0[s]);
            uint32_t a3 = __float_as_uint(A11 * S1[s]);
#pragma unroll
            for (int nr = 0; nr < 2; nr++) {
                uint2 bb = *(const uint2*)&resp_s[nl][nr * 8 + g][8 * s + 2 * tig];
                mma_tf32(acc[nr], a0, a1, a2, a3, bb.x, bb.y);
            }
        }
    }

#pragma unroll
    for (int nr = 0; nr < 2; nr++) {
        int u = nr * 8 + 2 * tig;
        atomicAdd(&out[b_r0 * U_ + u],           acc[nr][0]);
        atomicAdd(&out[b_r0 * U_ + u + 1],       acc[nr][1]);
        atomicAdd(&out[(b_r0 + 8) * U_ + u],     acc[nr][2]);
        atomicAdd(&out[(b_r0 + 8) * U_ + u + 1], acc[nr][3]);
    }
}

// ---------------------------------------------------------------------------
extern "C" void kernel_launch(void* const* d_in, const int* in_sizes, int n_in,
                              void* d_out, int out_size) {
    const float* x    = (const float*)d_in[0];  // [B, I]
    const float* fsl  = (const float*)d_in[1];  // [I, N, D]
    const float* th   = (const float*)d_in[2];  // [N, D]
    const float* lt   = (const float*)d_in[3];  // [N, D]
    const float* resp = (const float*)d_in[4];  // [N, U, 2^D]
    float* out = (float*)d_out;                 // [B, U]

    k_prep<<<512, 256>>>(fsl, x, out);
    k_gemm<<<dim3(B_ / 64, ND_ / 128), 256>>>(resp, th, lt);
    k_forest<<<dim3(B_ / 128, N_ / 4), 256>>>(out);
}